// round 1
// baseline (speedup 1.0000x reference)
#include <cuda_runtime.h>
#include <math.h>

// Problem constants
#define NROW 32768          // BS*NAG
#define BSB  4096           // BS
#define HID  256
#define NACT 16
#define MESS 64
#define TRAJD 80            // STEPS*NACT
#define STEPS 5

// ---------------- scratch (static device globals; no allocation) -------------
__device__ float g_x   [NROW * 256];
__device__ float g_gi  [NROW * 768];
__device__ float g_gh  [NROW * 768];
__device__ float g_hc0 [NROW * 256];
__device__ float g_hc1 [NROW * 256];
__device__ float g_traj[NROW * TRAJD];
__device__ float g_ac  [NROW];
__device__ float g_q   [NROW * 64];
__device__ float g_k   [NROW * 64];
__device__ float g_v   [NROW * 64];
__device__ float g_msg [NROW * 64];

// ---------------- generic tiled SGEMM:  C[M,N] = A[M,K] @ B[N,:K]^T + bias ---
// B row stride = ldb (>= K).  EPI: 0 none, 1 relu, 2 trans-tail (adds the
// 8-column action concat:  C[m,n] += sum_j ac[batch(m)*8+j] * B[n, 256+j]).
#define EPI_NONE  0
#define EPI_RELU  1
#define EPI_TRANS 2

template <int EPI>
__global__ __launch_bounds__(256, 2)
void sgemm_kernel(const float* __restrict__ A, const float* __restrict__ B,
                  const float* __restrict__ bias, float* __restrict__ C,
                  int M, int N, int K, int ldb, const float* __restrict__ ac)
{
    constexpr int BM = 128, BN = 64, BK = 16, TM = 8, TN = 4;
    __shared__ float As[BK][BM];
    __shared__ float Bs[BK][BN];
    __shared__ float s_tail[8][BN];
    __shared__ float s_ac[BM];

    const int tid = threadIdx.x;
    const int bm = blockIdx.y * BM;
    const int bn = blockIdx.x * BN;

    if (EPI == EPI_TRANS) {
        for (int t = tid; t < 8 * BN; t += 256) {
            int j = t / BN, n = t % BN;
            s_tail[j][n] = B[(size_t)(bn + n) * ldb + 256 + j];
        }
        if (tid < BM) s_ac[tid] = ac[bm + tid];
    }

    float acc[TM][TN];
#pragma unroll
    for (int i = 0; i < TM; i++)
#pragma unroll
        for (int j = 0; j < TN; j++) acc[i][j] = 0.f;

    const int arow  = tid >> 2;      // 0..63
    const int acol4 = tid & 3;       // 0..3  (group of 4 k's)
    const int tx = tid & 15, ty = tid >> 4;

    for (int kt = 0; kt < K; kt += BK) {
        float4 a0 = *(const float4*)(A + (size_t)(bm + arow)      * K + kt + acol4 * 4);
        float4 a1 = *(const float4*)(A + (size_t)(bm + arow + 64) * K + kt + acol4 * 4);
        float4 b0 = *(const float4*)(B + (size_t)(bn + arow)      * ldb + kt + acol4 * 4);
        __syncthreads();
        As[acol4 * 4 + 0][arow] = a0.x; As[acol4 * 4 + 1][arow] = a0.y;
        As[acol4 * 4 + 2][arow] = a0.z; As[acol4 * 4 + 3][arow] = a0.w;
        As[acol4 * 4 + 0][arow + 64] = a1.x; As[acol4 * 4 + 1][arow + 64] = a1.y;
        As[acol4 * 4 + 2][arow + 64] = a1.z; As[acol4 * 4 + 3][arow + 64] = a1.w;
        Bs[acol4 * 4 + 0][arow] = b0.x; Bs[acol4 * 4 + 1][arow] = b0.y;
        Bs[acol4 * 4 + 2][arow] = b0.z; Bs[acol4 * 4 + 3][arow] = b0.w;
        __syncthreads();
#pragma unroll
        for (int kk = 0; kk < BK; kk++) {
            const float4 av0 = *(const float4*)&As[kk][ty * TM];
            const float4 av1 = *(const float4*)&As[kk][ty * TM + 4];
            const float4 bv  = *(const float4*)&Bs[kk][tx * TN];
            const float ar[8] = {av0.x, av0.y, av0.z, av0.w, av1.x, av1.y, av1.z, av1.w};
            const float br[4] = {bv.x, bv.y, bv.z, bv.w};
#pragma unroll
            for (int i = 0; i < TM; i++)
#pragma unroll
                for (int j = 0; j < TN; j++) acc[i][j] += ar[i] * br[j];
        }
    }

    // epilogue
    float bvv[4];
#pragma unroll
    for (int j = 0; j < 4; j++) bvv[j] = bias[bn + tx * 4 + j];

    float tailv[4] = {0.f, 0.f, 0.f, 0.f};
    if (EPI == EPI_TRANS) {
        // all TM rows of this thread belong to one batch (ty*8 aligned)
#pragma unroll
        for (int j = 0; j < 4; j++) {
            float s = 0.f;
#pragma unroll
            for (int jj = 0; jj < 8; jj++) s += s_ac[ty * 8 + jj] * s_tail[jj][tx * 4 + j];
            tailv[j] = s;
        }
    }

#pragma unroll
    for (int i = 0; i < TM; i++) {
        float4 o;
        float v0 = acc[i][0] + bvv[0] + tailv[0];
        float v1 = acc[i][1] + bvv[1] + tailv[1];
        float v2 = acc[i][2] + bvv[2] + tailv[2];
        float v3 = acc[i][3] + bvv[3] + tailv[3];
        if (EPI == EPI_RELU) {
            v0 = fmaxf(v0, 0.f); v1 = fmaxf(v1, 0.f);
            v2 = fmaxf(v2, 0.f); v3 = fmaxf(v3, 0.f);
        }
        o.x = v0; o.y = v1; o.z = v2; o.w = v3;
        *(float4*)(C + (size_t)(bm + ty * TM + i) * N + bn + tx * 4) = o;
    }
}

// ---------------- GRU gate fusion -------------------------------------------
__device__ __forceinline__ float gru1(float ir, float hr, float iz, float hz,
                                      float in_, float hn, float oh)
{
    float r = 1.f / (1.f + expf(-(ir + hr)));
    float z = 1.f / (1.f + expf(-(iz + hz)));
    float n = tanhf(in_ + r * hn);
    return (1.f - z) * n + z * oh;
}

__global__ void gru_gates_kernel(const float* __restrict__ gi, const float* __restrict__ gh,
                                 const float* __restrict__ oldh, float* __restrict__ h)
{
    int t = blockIdx.x * blockDim.x + threadIdx.x;   // over NROW*64 float4s
    if (t >= NROW * 64) return;
    int i = t >> 6, c = t & 63;
    const float4* gi4 = (const float4*)(gi + (size_t)i * 768);
    const float4* gh4 = (const float4*)(gh + (size_t)i * 768);
    float4 ir = gi4[c], iz = gi4[64 + c], in_ = gi4[128 + c];
    float4 hr = gh4[c], hz = gh4[64 + c], hn  = gh4[128 + c];
    float4 oh = ((const float4*)(oldh + (size_t)i * 256))[c];
    float4 o;
    o.x = gru1(ir.x, hr.x, iz.x, hz.x, in_.x, hn.x, oh.x);
    o.y = gru1(ir.y, hr.y, iz.y, hz.y, in_.y, hn.y, oh.y);
    o.z = gru1(ir.z, hr.z, iz.z, hz.z, in_.z, hn.z, oh.z);
    o.w = gru1(ir.w, hr.w, iz.w, hz.w, in_.w, hn.w, oh.w);
    ((float4*)(h + (size_t)i * 256))[c] = o;
}

// ---------------- dec GEMM (N=16) + argmax, warp per row --------------------
// traj[row*80 + step*16 + a] = hc[row,:] @ dec_w[a,:] + dec_b[a]
// ac[row] = argmax_a (first max)
__global__ __launch_bounds__(256)
void dec_argmax_kernel(const float* __restrict__ hc, const float* __restrict__ dec_w,
                       const float* __restrict__ dec_b, float* __restrict__ traj,
                       float* __restrict__ ac, int step, int write_ac)
{
    __shared__ float s_w[16][256];
    __shared__ float s_b[16];
    int tid = threadIdx.x;
    for (int t = tid; t < 16 * 256; t += 256) s_w[t >> 8][t & 255] = dec_w[t];
    if (tid < 16) s_b[tid] = dec_b[tid];
    __syncthreads();

    int warp = tid >> 5, lane = tid & 31;
    int row = blockIdx.x * 8 + warp;
    const float* hp = hc + (size_t)row * 256;

    float acc[16];
#pragma unroll
    for (int a = 0; a < 16; a++) acc[a] = 0.f;
#pragma unroll
    for (int i = 0; i < 8; i++) {
        int k = lane + i * 32;
        float v = hp[k];
#pragma unroll
        for (int a = 0; a < 16; a++) acc[a] += v * s_w[a][k];
    }
#pragma unroll
    for (int off = 16; off >= 1; off >>= 1)
#pragma unroll
        for (int a = 0; a < 16; a++)
            acc[a] += __shfl_xor_sync(0xffffffffu, acc[a], off);

    // every lane now holds all 16 totals
#pragma unroll
    for (int a = 0; a < 16; a++) {
        float o = acc[a] + s_b[a];
        if (lane == a) traj[(size_t)row * TRAJD + step * 16 + a] = o;
    }
    if (write_ac && lane == 0) {
        float bv = acc[0] + s_b[0]; int bi = 0;
#pragma unroll
        for (int a = 1; a < 16; a++) {
            float v = acc[a] + s_b[a];
            if (v > bv) { bv = v; bi = a; }
        }
        ac[row] = (float)bi;
    }
}

// ---------------- attention: one block per batch (8 agents) -----------------
__global__ __launch_bounds__(128)
void attn_kernel(const float* __restrict__ q, const float* __restrict__ k,
                 const float* __restrict__ v, float* __restrict__ msg)
{
    int b = blockIdx.x, tid = threadIdx.x;
    __shared__ float sq[8][64], sk[8][64], sv[8][64], sc[8][8];
    for (int t = tid; t < 512; t += 128) {
        sq[t >> 6][t & 63] = q[(size_t)b * 512 + t];
        sk[t >> 6][t & 63] = k[(size_t)b * 512 + t];
        sv[t >> 6][t & 63] = v[(size_t)b * 512 + t];
    }
    __syncthreads();
    if (tid < 64) {
        int n = tid >> 3, m = tid & 7;
        float s = 0.f;
#pragma unroll
        for (int d = 0; d < 64; d++) s += sq[n][d] * sk[m][d];
        sc[n][m] = s * 0.125f;     // / sqrt(MESS=64)
    }
    __syncthreads();
    if (tid < 8) {
        int n = tid;
        float mx = sc[n][0];
#pragma unroll
        for (int m = 1; m < 8; m++) mx = fmaxf(mx, sc[n][m]);
        float sum = 0.f;
#pragma unroll
        for (int m = 0; m < 8; m++) { float e = expf(sc[n][m] - mx); sc[n][m] = e; sum += e; }
        float inv = 1.f / sum;
#pragma unroll
        for (int m = 0; m < 8; m++) sc[n][m] *= inv;
    }
    __syncthreads();
    for (int t = tid; t < 512; t += 128) {
        int n = t >> 6, d = t & 63;
        float s = 0.f;
#pragma unroll
        for (int m = 0; m < 8; m++) s += sc[n][m] * sv[m][d];
        msg[(size_t)b * 512 + t] = s;
    }
}

// ---------------- final q: q = traj[:, :16] + 0.5*([h|msg]@qij_w^T + qij_b) --
__global__ __launch_bounds__(256)
void final_q_kernel(const float* __restrict__ h, const float* __restrict__ msg,
                    const float* __restrict__ traj, const float* __restrict__ qij_w,
                    const float* __restrict__ qij_b, float* __restrict__ qout)
{
    __shared__ float s_w[16][320];   // 20 KB
    __shared__ float s_b[16];
    int tid = threadIdx.x;
    for (int t = tid; t < 16 * 320; t += 256) s_w[t / 320][t % 320] = qij_w[t];
    if (tid < 16) s_b[tid] = qij_b[tid];
    __syncthreads();

    int warp = tid >> 5, lane = tid & 31;
    int row = blockIdx.x * 8 + warp;
    const float* hp = h   + (size_t)row * 256;
    const float* mp = msg + (size_t)row * 64;

    float acc[16];
#pragma unroll
    for (int a = 0; a < 16; a++) acc[a] = 0.f;
#pragma unroll
    for (int i = 0; i < 10; i++) {
        int kk = lane + i * 32;
        float v = (i < 8) ? hp[kk] : mp[kk - 256];
#pragma unroll
        for (int a = 0; a < 16; a++) acc[a] += v * s_w[a][kk];
    }
#pragma unroll
    for (int off = 16; off >= 1; off >>= 1)
#pragma unroll
        for (int a = 0; a < 16; a++)
            acc[a] += __shfl_xor_sync(0xffffffffu, acc[a], off);

#pragma unroll
    for (int a = 0; a < 16; a++) {
        float o = traj[(size_t)row * TRAJD + a] + 0.5f * (acc[a] + s_b[a]);
        if (lane == a) qout[(size_t)row * 16 + a] = o;
    }
}

// ---------------- driver -----------------------------------------------------
extern "C" void kernel_launch(void* const* d_in, const int* in_sizes, int n_in,
                              void* d_out, int out_size)
{
    const float* inputs  = (const float*)d_in[0];
    const float* old_h   = (const float*)d_in[1];
    const float* fc1_w   = (const float*)d_in[2];
    const float* fc1_b   = (const float*)d_in[3];
    const float* w_ih    = (const float*)d_in[4];
    const float* w_hh    = (const float*)d_in[5];
    const float* b_ih    = (const float*)d_in[6];
    const float* b_hh    = (const float*)d_in[7];
    const float* dec_w   = (const float*)d_in[8];
    const float* dec_b   = (const float*)d_in[9];
    const float* trans_w = (const float*)d_in[10];
    const float* trans_b = (const float*)d_in[11];
    const float* qij_w   = (const float*)d_in[12];
    const float* qij_b   = (const float*)d_in[13];
    const float* q_w     = (const float*)d_in[14];
    const float* q_b     = (const float*)d_in[15];
    const float* k_w     = (const float*)d_in[16];
    const float* k_b     = (const float*)d_in[17];
    const float* v_w     = (const float*)d_in[18];
    const float* v_b     = (const float*)d_in[19];

    float* q_out = (float*)d_out;                       // (NROW, 16)
    float* h_out = (float*)d_out + (size_t)NROW * 16;   // (NROW, 256)

    float *px, *pgi, *pgh, *phc0, *phc1, *ptraj, *pac, *pq, *pk, *pv, *pmsg;
    cudaGetSymbolAddress((void**)&px,    g_x);
    cudaGetSymbolAddress((void**)&pgi,   g_gi);
    cudaGetSymbolAddress((void**)&pgh,   g_gh);
    cudaGetSymbolAddress((void**)&phc0,  g_hc0);
    cudaGetSymbolAddress((void**)&phc1,  g_hc1);
    cudaGetSymbolAddress((void**)&ptraj, g_traj);
    cudaGetSymbolAddress((void**)&pac,   g_ac);
    cudaGetSymbolAddress((void**)&pq,    g_q);
    cudaGetSymbolAddress((void**)&pk,    g_k);
    cudaGetSymbolAddress((void**)&pv,    g_v);
    cudaGetSymbolAddress((void**)&pmsg,  g_msg);

    const int M = NROW;

    // 1. x = relu(inputs @ fc1_w^T + fc1_b)
    sgemm_kernel<EPI_RELU><<<dim3(256 / 64, M / 128), 256>>>(
        inputs, fc1_w, fc1_b, px, M, 256, 128, 128, nullptr);
    // 2. gi = x @ w_ih^T + b_ih ; gh = old_h @ w_hh^T + b_hh
    sgemm_kernel<EPI_NONE><<<dim3(768 / 64, M / 128), 256>>>(
        px, w_ih, b_ih, pgi, M, 768, 256, 256, nullptr);
    sgemm_kernel<EPI_NONE><<<dim3(768 / 64, M / 128), 256>>>(
        old_h, w_hh, b_hh, pgh, M, 768, 256, 256, nullptr);
    // 3. GRU gates -> h (written straight into the output buffer)
    gru_gates_kernel<<<(NROW * 64) / 256, 256>>>(pgi, pgh, old_h, h_out);

    // 4. imagination rollout
    float* hcbuf[6];
    hcbuf[0] = h_out; hcbuf[1] = phc0; hcbuf[2] = phc1; hcbuf[3] = phc0; hcbuf[4] = phc1;
    for (int s = 0; s < STEPS; s++) {
        dec_argmax_kernel<<<NROW / 8, 256>>>(hcbuf[s], dec_w, dec_b, ptraj, pac, s,
                                             (s < STEPS - 1) ? 1 : 0);
        if (s < STEPS - 1) {
            sgemm_kernel<EPI_TRANS><<<dim3(256 / 64, M / 128), 256>>>(
                hcbuf[s], trans_w, trans_b, hcbuf[s + 1], M, 256, 256, 264, pac);
        }
    }

    // 5. q/k/v projections of the trajectory
    sgemm_kernel<EPI_NONE><<<dim3(1, M / 128), 256>>>(ptraj, q_w, q_b, pq, M, 64, 80, 80, nullptr);
    sgemm_kernel<EPI_NONE><<<dim3(1, M / 128), 256>>>(ptraj, k_w, k_b, pk, M, 64, 80, 80, nullptr);
    sgemm_kernel<EPI_NONE><<<dim3(1, M / 128), 256>>>(ptraj, v_w, v_b, pv, M, 64, 80, 80, nullptr);

    // 6. tiny 8x8 attention per batch
    attn_kernel<<<BSB, 128>>>(pq, pk, pv, pmsg);

    // 7. q = q_local + 0.5*q_ij  (q_local is traj[:, :16])
    final_q_kernel<<<NROW / 8, 256>>>(h_out, pmsg, ptraj, qij_w, qij_b, q_out);
}

// round 6
// speedup vs baseline: 1.2463x; 1.2463x over previous
#include <cuda_runtime.h>
#include <cuda_fp16.h>
#include <math.h>
#include <stdint.h>

#define NROW 32768
#define BSB  4096
#define STEPS 5
#define TRAJD 80

// ---------------- scratch (static device globals) ---------------------------
__device__ __half g_ae_in [(size_t)NROW * 384];
__device__ __half g_ae_x  [(size_t)NROW * 768];
__device__ __half g_ae_h  [(size_t)NROW * 768];
__device__ __half g_ae_hc0[(size_t)NROW * 832];
__device__ __half g_ae_hc1[(size_t)NROW * 832];
__device__ __half g_ae_tr [(size_t)NROW * 256];
__device__ __half g_be_fc1[256 * 384];
__device__ __half g_be_ih [768 * 768];
__device__ __half g_be_hh [768 * 768];
__device__ __half g_be_tra[256 * 832];
__device__ __half g_be_qkv[256 * 256];      // padded to 256 rows
__device__ float g_qkvb[192];
__device__ float g_gi  [(size_t)NROW * 768];
__device__ float g_gh  [(size_t)NROW * 768];
__device__ float g_traj[(size_t)NROW * TRAJD];
__device__ float g_ac  [NROW];
__device__ float g_qkv [(size_t)NROW * 192];
__device__ float g_msg [(size_t)NROW * 64];

// ---------------- PTX helpers ------------------------------------------------
__device__ __forceinline__ uint32_t smem_u32(const void* p) {
    uint32_t a;
    asm("{ .reg .u64 t; cvta.to.shared.u64 t, %1; cvt.u32.u64 %0, t; }" : "=r"(a) : "l"(p));
    return a;
}
__device__ __forceinline__ void cpa16(uint32_t s, const void* g) {
    asm volatile("cp.async.cg.shared.global [%0], [%1], 16;" :: "r"(s), "l"(g));
}
__device__ __forceinline__ void cpa_commit() { asm volatile("cp.async.commit_group;" ::: "memory"); }
template <int N> __device__ __forceinline__ void cpa_wait() {
    asm volatile("cp.async.wait_group %0;" :: "n"(N) : "memory");
}
__device__ __forceinline__ void ldsm4(uint32_t* r, uint32_t addr) {
    asm volatile("ldmatrix.sync.aligned.m8n8.x4.shared.b16 {%0,%1,%2,%3}, [%4];"
                 : "=r"(r[0]), "=r"(r[1]), "=r"(r[2]), "=r"(r[3]) : "r"(addr));
}
__device__ __forceinline__ void mma16816(float* d, const uint32_t* a, const uint32_t* b) {
    asm volatile("mma.sync.aligned.m16n8k16.row.col.f32.f16.f16.f32 "
                 "{%0,%1,%2,%3}, {%4,%5,%6,%7}, {%8,%9}, {%0,%1,%2,%3};"
                 : "+f"(d[0]), "+f"(d[1]), "+f"(d[2]), "+f"(d[3])
                 : "r"(a[0]), "r"(a[1]), "r"(a[2]), "r"(a[3]), "r"(b[0]), "r"(b[1]));
}
__device__ __forceinline__ uint32_t swz(uint32_t b) { return b ^ ((b >> 3) & 0x70); }

// ---------------- HMMA GEMM --------------------------------------------------
// C[M,Nreal] = Ae[M,Kp] @ Be[Npad,Kp]^T + bias ; fp16 in, fp32 accum.
// EPI 0: fp32 out (ldc). EPI 1: relu + split-fp16 out. EPI 2: split-fp16 out.
// BM=128, BN=128, BK=64. 256 threads (8 warps, 4(M) x 2(N)), warp tile 32x64.
#define STAGE_BYTES 32768
#define SMEM_TOTAL_MM (2 * STAGE_BYTES)

template <int EPI>
__global__ __launch_bounds__(256, 2)
void mm_gemm(const __half* __restrict__ Ae, const __half* __restrict__ Be,
             const float* __restrict__ bias, float* __restrict__ C, int ldc,
             __half* __restrict__ Aout, int split_k, int split_ld,
             int Nreal, int Kp)
{
    extern __shared__ char smem[];
    const uint32_t sbase = smem_u32(smem);
    const int tid = threadIdx.x, wid = tid >> 5, lane = tid & 31;
    const int warp_m = wid & 3, warp_n = wid >> 2;
    const int bm = blockIdx.y * 128;
    const int bn = blockIdx.x * 128;
    const int nc = Kp >> 6;

    float acc[2][8][4];
#pragma unroll
    for (int mf = 0; mf < 2; mf++)
#pragma unroll
        for (int nf = 0; nf < 8; nf++)
#pragma unroll
            for (int j = 0; j < 4; j++) acc[mf][nf][j] = 0.f;

    auto load_chunk = [&](int c, int s) {
        const uint32_t ab = sbase + s * STAGE_BYTES;
        const uint32_t bb = ab + 16384;
        const __half* Ap = Ae + (size_t)bm * Kp + c * 64;
        const __half* Bp = Be + (size_t)bn * Kp + c * 64;
#pragma unroll
        for (int t4 = 0; t4 < 4; t4++) {
            int t = tid + t4 * 256;
            int r = t >> 3, cc = t & 7;
            cpa16(ab + swz(r * 128 + cc * 16), Ap + (size_t)r * Kp + cc * 8);
        }
#pragma unroll
        for (int t4 = 0; t4 < 4; t4++) {
            int t = tid + t4 * 256;
            int r = t >> 3, cc = t & 7;
            cpa16(bb + swz(r * 128 + cc * 16), Bp + (size_t)r * Kp + cc * 8);
        }
        cpa_commit();
    };

    load_chunk(0, 0);
    for (int i = 0; i < nc; i++) {
        if (i + 1 < nc) { load_chunk(i + 1, (i + 1) & 1); cpa_wait<1>(); }
        else            { cpa_wait<0>(); }
        __syncthreads();

        const uint32_t a_s = sbase + (i & 1) * STAGE_BYTES;
        const uint32_t b_s = a_s + 16384;
#pragma unroll
        for (int kk = 0; kk < 4; kk++) {
            uint32_t af[2][4], bf[8][2];
#pragma unroll
            for (int mf = 0; mf < 2; mf++) {
                int row = warp_m * 32 + mf * 16 + (lane & 15);
                int colb = kk * 32 + ((lane >> 4) << 4);
                ldsm4(af[mf], a_s + swz(row * 128 + colb));
            }
#pragma unroll
            for (int np = 0; np < 4; np++) {
                // non-trans ldmatrix: matrices = (n0-7,k0-7),(n0-7,k8-15),(n8-15,k0-7),(n8-15,k8-15)
                int row = warp_n * 64 + np * 16 + ((lane >> 4) << 3) + (lane & 7);
                int colb = kk * 32 + ((lane & 8) ? 16 : 0);
                uint32_t r[4];
                ldsm4(r, b_s + swz(row * 128 + colb));
                bf[np * 2][0] = r[0]; bf[np * 2][1] = r[1];
                bf[np * 2 + 1][0] = r[2]; bf[np * 2 + 1][1] = r[3];
            }
#pragma unroll
            for (int mf = 0; mf < 2; mf++)
#pragma unroll
                for (int nf = 0; nf < 8; nf++)
                    mma16816(acc[mf][nf], af[mf], bf[nf]);
        }
        __syncthreads();
    }

    // ---- epilogue ----
#pragma unroll
    for (int mf = 0; mf < 2; mf++) {
        const int r0 = bm + warp_m * 32 + mf * 16 + (lane >> 2);
#pragma unroll
        for (int nf = 0; nf < 8; nf++) {
            const int n0 = bn + warp_n * 64 + nf * 8 + (lane & 3) * 2;
            if (n0 >= Nreal) continue;
            const float b0 = __ldg(bias + n0), b1 = __ldg(bias + n0 + 1);
            if (EPI == 0) {
                float2 v0 = {acc[mf][nf][0] + b0, acc[mf][nf][1] + b1};
                float2 v1 = {acc[mf][nf][2] + b0, acc[mf][nf][3] + b1};
                *(float2*)(C + (size_t)r0 * ldc + n0) = v0;
                *(float2*)(C + (size_t)(r0 + 8) * ldc + n0) = v1;
            } else {
#pragma unroll
                for (int e = 0; e < 4; e++) {
                    float v = acc[mf][nf][e] + ((e & 1) ? b1 : b0);
                    if (EPI == 1) v = fmaxf(v, 0.f);
                    __half hi = __float2half(v);
                    __half lo = __float2half(v - __half2float(hi));
                    int rr = r0 + (e >> 1) * 8;
                    int col = n0 + (e & 1);
                    __half* ap = Aout + (size_t)rr * split_ld;
                    ap[col] = hi; ap[split_k + col] = hi; ap[2 * split_k + col] = lo;
                }
            }
        }
    }
}

// ---------------- split kernels ---------------------------------------------
// A-side: [hi | hi | lo] ; B-side: [hi | lo | hi]. Row pitch Kp halves.
__global__ void split_a(const float* __restrict__ A, __half* __restrict__ Ae,
                        int K, int Kp, int Mtot)
{
    int K2 = K >> 1;
    int t = blockIdx.x * blockDim.x + threadIdx.x;
    if (t >= Mtot * K2) return;
    int m = t / K2, c2 = t - m * K2;
    float2 v = ((const float2*)A)[t];
    __half hx = __float2half(v.x), hy = __float2half(v.y);
    __half2 hi; hi.x = hx; hi.y = hy;
    __half2 lo;
    lo.x = __float2half(v.x - __half2float(hx));
    lo.y = __float2half(v.y - __half2float(hy));
    __half2* row = (__half2*)(Ae + (size_t)m * Kp);
    row[c2] = hi; row[K2 + c2] = hi; row[2 * K2 + c2] = lo;
}

__global__ void split_b(const float* __restrict__ B, __half* __restrict__ Be,
                        int K, int Kp, int Ntot)
{
    int K2 = K >> 1;
    int t = blockIdx.x * blockDim.x + threadIdx.x;
    if (t >= Ntot * K2) return;
    int m = t / K2, c2 = t - m * K2;
    float2 v = ((const float2*)B)[t];
    __half hx = __float2half(v.x), hy = __float2half(v.y);
    __half2 hi; hi.x = hx; hi.y = hy;
    __half2 lo;
    lo.x = __float2half(v.x - __half2float(hx));
    lo.y = __float2half(v.y - __half2float(hy));
    __half2* row = (__half2*)(Be + (size_t)m * Kp);
    row[c2] = hi; row[K2 + c2] = lo; row[2 * K2 + c2] = hi;
}

__global__ void zero_pad(__half* __restrict__ p, int ld, int start, int end, int rows)
{
    int w = end - start;
    int t = blockIdx.x * blockDim.x + threadIdx.x;
    if (t >= rows * w) return;
    int m = t / w, c = t - m * w;
    p[(size_t)m * ld + start + c] = __float2half(0.f);
}

// ---------------- GRU gates (emits fp32 h + split-fp16 hc in trans layout) --
__device__ __forceinline__ float gru1(float ir, float hr, float iz, float hz,
                                      float in_, float hn, float oh)
{
    float r = 1.f / (1.f + expf(-(ir + hr)));
    float z = 1.f / (1.f + expf(-(iz + hz)));
    float n = tanhf(in_ + r * hn);
    return (1.f - z) * n + z * oh;
}

__global__ void gru_gates_kernel(const float* __restrict__ gi, const float* __restrict__ gh,
                                 const float* __restrict__ oldh, float* __restrict__ h,
                                 __half* __restrict__ ae)
{
    int t = blockIdx.x * blockDim.x + threadIdx.x;
    if (t >= NROW * 64) return;
    int i = t >> 6, c = t & 63;
    const float4* gi4 = (const float4*)(gi + (size_t)i * 768);
    const float4* gh4 = (const float4*)(gh + (size_t)i * 768);
    float4 ir = gi4[c], iz = gi4[64 + c], in_ = gi4[128 + c];
    float4 hr = gh4[c], hz = gh4[64 + c], hn = gh4[128 + c];
    float4 oh = ((const float4*)(oldh + (size_t)i * 256))[c];
    float4 o;
    o.x = gru1(ir.x, hr.x, iz.x, hz.x, in_.x, hn.x, oh.x);
    o.y = gru1(ir.y, hr.y, iz.y, hz.y, in_.y, hn.y, oh.y);
    o.z = gru1(ir.z, hr.z, iz.z, hz.z, in_.z, hn.z, oh.z);
    o.w = gru1(ir.w, hr.w, iz.w, hz.w, in_.w, hn.w, oh.w);
    ((float4*)(h + (size_t)i * 256))[c] = o;
    __half* ap = ae + (size_t)i * 832;
    int j = c * 4;
    float vv[4] = {o.x, o.y, o.z, o.w};
#pragma unroll
    for (int u = 0; u < 4; u++) {
        __half hi = __float2half(vv[u]);
        __half lo = __float2half(vv[u] - __half2float(hi));
        ap[j + u] = hi; ap[264 + j + u] = hi; ap[528 + j + u] = lo;
    }
}

// ---------------- dec GEMM (N=16) + argmax, warp per row --------------------
__global__ __launch_bounds__(256)
void dec_argmax_kernel(const __half* __restrict__ hbuf, const float* __restrict__ dec_w,
                       const float* __restrict__ dec_b, float* __restrict__ traj,
                       float* __restrict__ ac, int step, int write_ac)
{
    __shared__ float s_w[16][256];
    __shared__ float s_b[16];
    int tid = threadIdx.x;
    for (int t = tid; t < 16 * 256; t += 256) s_w[t >> 8][t & 255] = dec_w[t];
    if (tid < 16) s_b[tid] = dec_b[tid];
    __syncthreads();

    int warp = tid >> 5, lane = tid & 31;
    int row = blockIdx.x * 8 + warp;
    const __half* hp = hbuf + (size_t)row * 832;

    float acc[16];
#pragma unroll
    for (int a = 0; a < 16; a++) acc[a] = 0.f;
#pragma unroll
    for (int i = 0; i < 8; i++) {
        int k = lane + i * 32;
        float v = __half2float(hp[k]) + __half2float(hp[528 + k]);
#pragma unroll
        for (int a = 0; a < 16; a++) acc[a] += v * s_w[a][k];
    }
#pragma unroll
    for (int off = 16; off >= 1; off >>= 1)
#pragma unroll
        for (int a = 0; a < 16; a++)
            acc[a] += __shfl_xor_sync(0xffffffffu, acc[a], off);

#pragma unroll
    for (int a = 0; a < 16; a++) {
        float o = acc[a] + s_b[a];
        if (lane == a) traj[(size_t)row * TRAJD + step * 16 + a] = o;
    }
    if (write_ac && lane == 0) {
        float bv = acc[0] + s_b[0]; int bi = 0;
#pragma unroll
        for (int a = 1; a < 16; a++) {
            float v = acc[a] + s_b[a];
            if (v > bv) { bv = v; bi = a; }
        }
        ac[row] = (float)bi;
    }
}

// ---------------- scatter actions + pads into split hc buffer ---------------
__global__ void scatter_ac_kernel(const float* __restrict__ ac, __half* __restrict__ ae)
{
    int row = blockIdx.x * blockDim.x + threadIdx.x;
    if (row >= NROW) return;
    int b = row >> 3;
    __half* ap = ae + (size_t)row * 832;
    __half z = __float2half(0.f);
#pragma unroll
    for (int j = 0; j < 8; j++) {
        __half a = __float2half(ac[b * 8 + j]);
        ap[256 + j] = a; ap[520 + j] = a; ap[784 + j] = z;
    }
    for (int j = 792; j < 832; j++) ap[j] = z;
}

// ---------------- attention: one block per batch, combined qkv (ld=192) -----
__global__ __launch_bounds__(128)
void attn_kernel(const float* __restrict__ qkv, float* __restrict__ msg)
{
    int b = blockIdx.x, tid = threadIdx.x;
    __shared__ float sq[8][64], sk[8][64], sv[8][64], sc[8][8];
    for (int t = tid; t < 512; t += 128) {
        int n = t >> 6, d = t & 63;
        size_t base = ((size_t)b * 8 + n) * 192;
        sq[n][d] = qkv[base + d];
        sk[n][d] = qkv[base + 64 + d];
        sv[n][d] = qkv[base + 128 + d];
    }
    __syncthreads();
    if (tid < 64) {
        int n = tid >> 3, m = tid & 7;
        float s = 0.f;
#pragma unroll
        for (int d = 0; d < 64; d++) s += sq[n][d] * sk[m][d];
        sc[n][m] = s * 0.125f;
    }
    __syncthreads();
    if (tid < 8) {
        int n = tid;
        float mx = sc[n][0];
#pragma unroll
        for (int m = 1; m < 8; m++) mx = fmaxf(mx, sc[n][m]);
        float sum = 0.f;
#pragma unroll
        for (int m = 0; m < 8; m++) { float e = expf(sc[n][m] - mx); sc[n][m] = e; sum += e; }
        float inv = 1.f / sum;
#pragma unroll
        for (int m = 0; m < 8; m++) sc[n][m] *= inv;
    }
    __syncthreads();
    for (int t = tid; t < 512; t += 128) {
        int n = t >> 6, d = t & 63;
        float s = 0.f;
#pragma unroll
        for (int m = 0; m < 8; m++) s += sc[n][m] * sv[m][d];
        msg[(size_t)b * 512 + t] = s;
    }
}

// ---------------- final q ----------------------------------------------------
__global__ __launch_bounds__(256)
void final_q_kernel(const float* __restrict__ h, const float* __restrict__ msg,
                    const float* __restrict__ traj, const float* __restrict__ qij_w,
                    const float* __restrict__ qij_b, float* __restrict__ qout)
{
    __shared__ float s_w[16][320];
    __shared__ float s_b[16];
    int tid = threadIdx.x;
    for (int t = tid; t < 16 * 320; t += 256) s_w[t / 320][t % 320] = qij_w[t];
    if (tid < 16) s_b[tid] = qij_b[tid];
    __syncthreads();

    int warp = tid >> 5, lane = tid & 31;
    int row = blockIdx.x * 8 + warp;
    const float* hp = h + (size_t)row * 256;
    const float* mp = msg + (size_t)row * 64;

    float acc[16];
#pragma unroll
    for (int a = 0; a < 16; a++) acc[a] = 0.f;
#pragma unroll
    for (int i = 0; i < 10; i++) {
        int kk = lane + i * 32;
        float v = (i < 8) ? hp[kk] : mp[kk - 256];
#pragma unroll
        for (int a = 0; a < 16; a++) acc[a] += v * s_w[a][kk];
    }
#pragma unroll
    for (int off = 16; off >= 1; off >>= 1)
#pragma unroll
        for (int a = 0; a < 16; a++)
            acc[a] += __shfl_xor_sync(0xffffffffu, acc[a], off);

#pragma unroll
    for (int a = 0; a < 16; a++) {
        float o = traj[(size_t)row * TRAJD + a] + 0.5f * (acc[a] + s_b[a]);
        if (lane == a) qout[(size_t)row * 16 + a] = o;
    }
}

// ---------------- driver -----------------------------------------------------
extern "C" void kernel_launch(void* const* d_in, const int* in_sizes, int n_in,
                              void* d_out, int out_size)
{
    const float* inputs  = (const float*)d_in[0];
    const float* old_h   = (const float*)d_in[1];
    const float* fc1_w   = (const float*)d_in[2];
    const float* fc1_b   = (const float*)d_in[3];
    const float* w_ih    = (const float*)d_in[4];
    const float* w_hh    = (const float*)d_in[5];
    const float* b_ih    = (const float*)d_in[6];
    const float* b_hh    = (const float*)d_in[7];
    const float* dec_w   = (const float*)d_in[8];
    const float* dec_b   = (const float*)d_in[9];
    const float* trans_w = (const float*)d_in[10];
    const float* trans_b = (const float*)d_in[11];
    const float* qij_w   = (const float*)d_in[12];
    const float* qij_b   = (const float*)d_in[13];
    const float* q_w     = (const float*)d_in[14];
    const float* q_b     = (const float*)d_in[15];
    const float* k_w     = (const float*)d_in[16];
    const float* k_b     = (const float*)d_in[17];
    const float* v_w     = (const float*)d_in[18];
    const float* v_b     = (const float*)d_in[19];

    float* q_out = (float*)d_out;
    float* h_out = (float*)d_out + (size_t)NROW * 16;

    __half *ae_in, *ae_x, *ae_h, *ae_hc0, *ae_hc1, *ae_tr;
    __half *be_fc1, *be_ih, *be_hh, *be_tra, *be_qkv;
    float *qkvb, *gi, *gh, *traj, *ac, *qkv, *msg;
    cudaGetSymbolAddress((void**)&ae_in, g_ae_in);
    cudaGetSymbolAddress((void**)&ae_x,  g_ae_x);
    cudaGetSymbolAddress((void**)&ae_h,  g_ae_h);
    cudaGetSymbolAddress((void**)&ae_hc0, g_ae_hc0);
    cudaGetSymbolAddress((void**)&ae_hc1, g_ae_hc1);
    cudaGetSymbolAddress((void**)&ae_tr, g_ae_tr);
    cudaGetSymbolAddress((void**)&be_fc1, g_be_fc1);
    cudaGetSymbolAddress((void**)&be_ih, g_be_ih);
    cudaGetSymbolAddress((void**)&be_hh, g_be_hh);
    cudaGetSymbolAddress((void**)&be_tra, g_be_tra);
    cudaGetSymbolAddress((void**)&be_qkv, g_be_qkv);
    cudaGetSymbolAddress((void**)&qkvb, g_qkvb);
    cudaGetSymbolAddress((void**)&gi, g_gi);
    cudaGetSymbolAddress((void**)&gh, g_gh);
    cudaGetSymbolAddress((void**)&traj, g_traj);
    cudaGetSymbolAddress((void**)&ac, g_ac);
    cudaGetSymbolAddress((void**)&qkv, g_qkv);
    cudaGetSymbolAddress((void**)&msg, g_msg);

    cudaFuncSetAttribute(mm_gemm<0>, cudaFuncAttributeMaxDynamicSharedMemorySize, SMEM_TOTAL_MM);
    cudaFuncSetAttribute(mm_gemm<1>, cudaFuncAttributeMaxDynamicSharedMemorySize, SMEM_TOTAL_MM);
    cudaFuncSetAttribute(mm_gemm<2>, cudaFuncAttributeMaxDynamicSharedMemorySize, SMEM_TOTAL_MM);

    auto grid1 = [](int n) { return (n + 255) / 256; };

    // ---- weight prep ----
    split_b<<<grid1(256 * 64), 256>>>(fc1_w, be_fc1, 128, 384, 256);
    split_b<<<grid1(768 * 128), 256>>>(w_ih, be_ih, 256, 768, 768);
    split_b<<<grid1(768 * 128), 256>>>(w_hh, be_hh, 256, 768, 768);
    split_b<<<grid1(256 * 132), 256>>>(trans_w, be_tra, 264, 832, 256);
    zero_pad<<<grid1(256 * 40), 256>>>(be_tra, 832, 792, 832, 256);
    split_b<<<grid1(64 * 40), 256>>>(q_w, be_qkv, 80, 256, 64);
    split_b<<<grid1(64 * 40), 256>>>(k_w, be_qkv + (size_t)64 * 256, 80, 256, 64);
    split_b<<<grid1(64 * 40), 256>>>(v_w, be_qkv + (size_t)128 * 256, 80, 256, 64);
    zero_pad<<<grid1(192 * 16), 256>>>(be_qkv, 256, 240, 256, 192);           // pad cols
    zero_pad<<<grid1(64 * 256), 256>>>(be_qkv + (size_t)192 * 256, 256, 0, 256, 64); // pad rows
    cudaMemcpyAsync(qkvb, q_b, 64 * sizeof(float), cudaMemcpyDeviceToDevice, 0);
    cudaMemcpyAsync(qkvb + 64, k_b, 64 * sizeof(float), cudaMemcpyDeviceToDevice, 0);
    cudaMemcpyAsync(qkvb + 128, v_b, 64 * sizeof(float), cudaMemcpyDeviceToDevice, 0);

    // ---- activation splits ----
    split_a<<<grid1(NROW * 64), 256>>>(inputs, ae_in, 128, 384, NROW);
    split_a<<<grid1(NROW * 128), 256>>>(old_h, ae_h, 256, 768, NROW);

    // ---- fc1 (relu + split into ae_x) ----
    mm_gemm<1><<<dim3(2, 256), 256, SMEM_TOTAL_MM>>>(
        ae_in, be_fc1, fc1_b, nullptr, 0, ae_x, 256, 768, 256, 384);
    // ---- gi / gh ----
    mm_gemm<0><<<dim3(6, 256), 256, SMEM_TOTAL_MM>>>(
        ae_x, be_ih, b_ih, gi, 768, nullptr, 0, 0, 768, 768);
    mm_gemm<0><<<dim3(6, 256), 256, SMEM_TOTAL_MM>>>(
        ae_h, be_hh, b_hh, gh, 768, nullptr, 0, 0, 768, 768);
    // ---- GRU gates -> h_out + split hc0 ----
    gru_gates_kernel<<<(NROW * 64) / 256, 256>>>(gi, gh, old_h, h_out, ae_hc0);

    // ---- imagination rollout ----
    for (int s = 0; s < STEPS; s++) {
        __half* cur = (s & 1) ? ae_hc1 : ae_hc0;
        __half* nxt = (s & 1) ? ae_hc0 : ae_hc1;
        dec_argmax_kernel<<<NROW / 8, 256>>>(cur, dec_w, dec_b, traj, ac, s,
                                             (s < STEPS - 1) ? 1 : 0);
        if (s < STEPS - 1) {
            scatter_ac_kernel<<<NROW / 256, 256>>>(ac, cur);
            mm_gemm<2><<<dim3(2, 256), 256, SMEM_TOTAL_MM>>>(
                cur, be_tra, trans_b, nullptr, 0, nxt, 264, 832, 256, 832);
        }
    }

    // ---- qkv ----
    split_a<<<grid1(NROW * 40), 256>>>(traj, ae_tr, 80, 256, NROW);
    zero_pad<<<grid1(NROW * 16), 256>>>(ae_tr, 256, 240, 256, NROW);
    mm_gemm<0><<<dim3(2, 256), 256, SMEM_TOTAL_MM>>>(
        ae_tr, be_qkv, qkvb, qkv, 192, nullptr, 0, 0, 192, 256);

    // ---- attention + final ----
    attn_kernel<<<BSB, 128>>>(qkv, msg);
    final_q_kernel<<<NROW / 8, 256>>>(h_out, msg, traj, qij_w, qij_b, q_out);
}